// round 3
// baseline (speedup 1.0000x reference)
#include <cuda_runtime.h>
#include <math.h>

#define ROWS      4096
#define COLS      8192
#define BCOLS     8           // columns per block (2 float4 per row)
#define NTHREADS  256
#define RG        128         // row groups = NTHREADS / 2 quad-lanes
#define CAP       256         // candidate capacity per column (expected ~3)

// Exact sparsemax along axis 0 of z = -exp(a) * x.
// Per column: tau in [max-1, max); the support set {z > tau} is tiny, so:
//   pass 1: column max (DRAM read, 128 MB)
//   pass 2: re-read (L2-hot) gathering z >= max-1 + zero-fill output (write)
//   solve : exact tau on the tiny candidate set in smem
//   scatter: write the ~3 nonzero outputs per column
__global__ void __launch_bounds__(NTHREADS)
sparsemax_kernel(const float* __restrict__ x, const float* __restrict__ a_ptr,
                 float* __restrict__ out)
{
    extern __shared__ unsigned char smem_raw[];
    float* s_val = reinterpret_cast<float*>(smem_raw);            // [BCOLS][CAP]
    int*   s_idx = reinterpret_cast<int*>(s_val + BCOLS * CAP);   // [BCOLS][CAP]
    __shared__ int   s_cnt[BCOLS];
    __shared__ float s_part[8][BCOLS];   // per-warp partial maxes
    __shared__ float s_thr[BCOLS];
    __shared__ float s_tau[BCOLS];

    const int tid  = threadIdx.x;
    const int tx   = tid & 1;            // which float4 of the 8-col group
    const int ty   = tid >> 1;           // row group 0..127
    const int warp = tid >> 5;
    const int lane = tid & 31;
    const int col0 = blockIdx.x * BCOLS;
    const float s  = -expf(a_ptr[0]);

    const float4* __restrict__ xin =
        reinterpret_cast<const float4*>(x) + (size_t)(col0 >> 2) + tx;
    float4* __restrict__ oout =
        reinterpret_cast<float4*>(out) + (size_t)(col0 >> 2) + tx;
    const int ld4 = COLS >> 2;           // 2048 float4 per row

    // ---------- Pass 1: per-column max of z = s*x (cold DRAM read) ----------
    float m0 = -INFINITY, m1 = -INFINITY, m2 = -INFINITY, m3 = -INFINITY;
    #pragma unroll 8
    for (int r = ty; r < ROWS; r += RG) {
        float4 v = xin[(size_t)r * ld4];
        m0 = fmaxf(m0, s * v.x);
        m1 = fmaxf(m1, s * v.y);
        m2 = fmaxf(m2, s * v.z);
        m3 = fmaxf(m3, s * v.w);
    }
    // warp reduce over the 16 lanes sharing this lane's parity (same tx)
    #pragma unroll
    for (int off = 16; off >= 2; off >>= 1) {
        m0 = fmaxf(m0, __shfl_xor_sync(0xFFFFFFFFu, m0, off));
        m1 = fmaxf(m1, __shfl_xor_sync(0xFFFFFFFFu, m1, off));
        m2 = fmaxf(m2, __shfl_xor_sync(0xFFFFFFFFu, m2, off));
        m3 = fmaxf(m3, __shfl_xor_sync(0xFFFFFFFFu, m3, off));
    }
    if (lane < 2) {                       // lane 0 -> tx 0, lane 1 -> tx 1
        s_part[warp][4 * tx + 0] = m0;
        s_part[warp][4 * tx + 1] = m1;
        s_part[warp][4 * tx + 2] = m2;
        s_part[warp][4 * tx + 3] = m3;
    }
    if (tid < BCOLS) s_cnt[tid] = 0;
    __syncthreads();

    if (tid < BCOLS) {
        float m = s_part[0][tid];
        #pragma unroll
        for (int w = 1; w < 8; w++) m = fmaxf(m, s_part[w][tid]);
        s_thr[tid] = m - 1.0f;            // tau >= max - 1 always
    }
    __syncthreads();

    // ---------- Pass 2: gather candidates (L2-hot read) + zero-fill out ----------
    const float t0 = s_thr[4 * tx + 0];
    const float t1 = s_thr[4 * tx + 1];
    const float t2 = s_thr[4 * tx + 2];
    const float t3 = s_thr[4 * tx + 3];
    const float4 zero4 = make_float4(0.f, 0.f, 0.f, 0.f);
    #pragma unroll 4
    for (int r = ty; r < ROWS; r += RG) {
        float4 v = xin[(size_t)r * ld4];
        oout[(size_t)r * ld4] = zero4;    // non-support outputs are exactly 0
        float z0 = s * v.x, z1 = s * v.y, z2 = s * v.z, z3 = s * v.w;
        if (z0 >= t0) { int i = atomicAdd(&s_cnt[4*tx+0], 1); if (i < CAP) { s_val[(4*tx+0)*CAP+i] = z0; s_idx[(4*tx+0)*CAP+i] = r; } }
        if (z1 >= t1) { int i = atomicAdd(&s_cnt[4*tx+1], 1); if (i < CAP) { s_val[(4*tx+1)*CAP+i] = z1; s_idx[(4*tx+1)*CAP+i] = r; } }
        if (z2 >= t2) { int i = atomicAdd(&s_cnt[4*tx+2], 1); if (i < CAP) { s_val[(4*tx+2)*CAP+i] = z2; s_idx[(4*tx+2)*CAP+i] = r; } }
        if (z3 >= t3) { int i = atomicAdd(&s_cnt[4*tx+3], 1); if (i < CAP) { s_val[(4*tx+3)*CAP+i] = z3; s_idx[(4*tx+3)*CAP+i] = r; } }
    }
    __syncthreads();

    // ---------- Solve: exact tau on the tiny candidate set ----------
    if (tid < BCOLS) {
        int n = min(s_cnt[tid], CAP);
        float* c  = &s_val[tid * CAP];
        int*   ci = &s_idx[tid * CAP];
        // insertion sort descending by value (n ~ 2-6), keep indices paired
        for (int i = 1; i < n; i++) {
            float key = c[i]; int keyi = ci[i];
            int j = i - 1;
            while (j >= 0 && c[j] < key) { c[j+1] = c[j]; ci[j+1] = ci[j]; j--; }
            c[j+1] = key; ci[j+1] = keyi;
        }
        // support scan: largest k with 1 + k*z_(k) > cumsum_k
        float csum = 0.0f, csk = 0.0f;
        int k = 1;
        for (int i = 0; i < n; i++) {
            csum += c[i];
            if (1.0f + (float)(i + 1) * c[i] > csum) { k = i + 1; csk = csum; }
        }
        s_tau[tid] = (csk - 1.0f) / (float)k;
    }
    __syncthreads();

    // ---------- Scatter: overwrite the few nonzero outputs ----------
    if (tid < BCOLS) {
        int n = min(s_cnt[tid], CAP);
        float tau = s_tau[tid];
        for (int i = 0; i < n; i++) {
            float o = s_val[tid * CAP + i] - tau;
            if (o > 0.0f)
                out[(size_t)s_idx[tid * CAP + i] * COLS + col0 + tid] = o;
        }
    }
}

extern "C" void kernel_launch(void* const* d_in, const int* in_sizes, int n_in,
                              void* d_out, int out_size)
{
    const float* x = (const float*)d_in[0];
    const float* a = (const float*)d_in[1];
    if (n_in >= 2 && in_sizes[0] == 1) {   // defensive on metadata order
        a = (const float*)d_in[0];
        x = (const float*)d_in[1];
    }

    // 48 KB dynamic smem (16.5 KB used): caps occupancy at 4 blocks/SM so the
    // concurrent working set (592 blocks x 128 KB = 74 MB) stays L2-resident
    // for the pass-2 re-read, while giving 32 warps/SM for latency cover.
    size_t shmem_req = 48 * 1024;
    cudaFuncSetAttribute(sparsemax_kernel,
                         cudaFuncAttributeMaxDynamicSharedMemorySize,
                         (int)shmem_req);

    sparsemax_kernel<<<COLS / BCOLS, NTHREADS, shmem_req>>>(x, a, (float*)d_out);
}